// round 5
// baseline (speedup 1.0000x reference)
#include <cuda_runtime.h>
#include <cuda_bf16.h>

#define T_      512
#define B_      512
#define EMB_    32
#define HID_    32
#define G4_     128   // 4*HID
#define FF_     16
#define NCLS_   7
#define VOCAB_  1000

// ---------------- scratch (static device memory; zero-init at load) ---------
__device__ float g_hs[(size_t)T_ * B_ * HID_]; // 32 MB hidden states

// ---------------- fast exp for softmax only ---------------------------------
__device__ __forceinline__ float ex2f(float x) {
    float r; asm("ex2.approx.f32 %0, %1;" : "=f"(r) : "f"(x)); return r;
}
__device__ __forceinline__ float sigm_acc(float x) { return 1.0f / (1.0f + expf(-x)); }

// ---- token dtype sniff: int64 tokens (<1000) have zero high words ----------
__device__ __forceinline__ bool x_is_i64(const int* __restrict__ x32) {
    return (x32[1] | x32[3] | x32[5] | x32[7] | x32[9]) == 0;
}
__device__ __forceinline__ int get_tok(const int* __restrict__ x32,
                                       bool i64, int idx) {
    return x32[i64 ? (idx << 1) : idx];
}

// ---------------- K2: LSTM, boring version ----------------------------------
// One warp per batch element. lane k owns h[k], c[k]. h exchanged via shfl.
// xg computed directly each step: xg[row] = W_ih[row,:]·emb[tok,:] + bsum[row].
__global__ __launch_bounds__(128) void k_lstm2(
    const int* __restrict__ x, const float* __restrict__ emb,
    const float* __restrict__ W_ih, const float* __restrict__ W_hh,
    const float* __restrict__ b_ih, const float* __restrict__ b_hh)
{
    __shared__ float Wih_s[G4_ * EMB_];   // 16 KB, rows x emb
    __shared__ float bsum_s[G4_];

    const int tid  = threadIdx.x;
    const int wid  = tid >> 5;
    const int lane = tid & 31;
    const int b    = blockIdx.x * 4 + wid;
    const bool i64 = x_is_i64(x);

#pragma unroll
    for (int i = 0; i < 32; ++i) Wih_s[tid + i * 128] = W_ih[tid + i * 128];
    if (tid < G4_) bsum_s[tid] = b_ih[tid] + b_hh[tid];
    __syncthreads();

    // recurrent weights in registers: rows lane, 32+lane, 64+lane, 96+lane
    float Wi[HID_], Wf[HID_], Wg[HID_], Wo[HID_];
#pragma unroll
    for (int j = 0; j < HID_; ++j) {
        Wi[j] = W_hh[(0 * HID_ + lane) * HID_ + j];
        Wf[j] = W_hh[(1 * HID_ + lane) * HID_ + j];
        Wg[j] = W_hh[(2 * HID_ + lane) * HID_ + j];
        Wo[j] = W_hh[(3 * HID_ + lane) * HID_ + j];
    }

    float h = 0.0f, c = 0.0f;

    for (int t = 0; t < T_; ++t) {
        const int tok = get_tok(x, i64, t * B_ + b);   // uniform across warp
        const float e_mine = emb[tok * EMB_ + lane];   // lane j holds e_j

        float ai = bsum_s[0 * HID_ + lane];
        float af = bsum_s[1 * HID_ + lane];
        float ag = bsum_s[2 * HID_ + lane];
        float ao = bsum_s[3 * HID_ + lane];

        // input projection: xg[row] += W_ih[row, j] * e_j
#pragma unroll
        for (int j = 0; j < EMB_; ++j) {
            const float ej = __shfl_sync(0xffffffffu, e_mine, j);
            ai = fmaf(Wih_s[(0 * HID_ + lane) * EMB_ + j], ej, ai);
            af = fmaf(Wih_s[(1 * HID_ + lane) * EMB_ + j], ej, af);
            ag = fmaf(Wih_s[(2 * HID_ + lane) * EMB_ + j], ej, ag);
            ao = fmaf(Wih_s[(3 * HID_ + lane) * EMB_ + j], ej, ao);
        }

        // recurrence: += W_hh[row, j] * h_j
#pragma unroll
        for (int j = 0; j < HID_; ++j) {
            const float hj = __shfl_sync(0xffffffffu, h, j);
            ai = fmaf(Wi[j], hj, ai);
            af = fmaf(Wf[j], hj, af);
            ag = fmaf(Wg[j], hj, ag);
            ao = fmaf(Wo[j], hj, ao);
        }

        const float ig = sigm_acc(ai);
        const float fg = sigm_acc(af);
        const float gg = tanhf(ag);
        const float og = sigm_acc(ao);
        c = fmaf(fg, c, ig * gg);
        h = og * tanhf(c);

        g_hs[((size_t)t * B_ + b) * HID_ + lane] = h;  // coalesced 128B/warp
    }
}

// ---------------- K3: FF + logits, boring version ---------------------------
__global__ __launch_bounds__(256) void k_ff2(
    const float* __restrict__ W1, const float* __restrict__ b1,
    const float* __restrict__ W2, const float* __restrict__ b2,
    float* __restrict__ out)
{
    const int r = blockIdx.x * 256 + threadIdx.x;      // flat row t*B+b
    float hv[HID_];
    const float4* hp = reinterpret_cast<const float4*>(&g_hs[(size_t)r * HID_]);
#pragma unroll
    for (int q = 0; q < HID_ / 4; ++q) {
        const float4 v = hp[q];
        hv[q * 4 + 0] = v.x; hv[q * 4 + 1] = v.y;
        hv[q * 4 + 2] = v.z; hv[q * 4 + 3] = v.w;
    }
    float z[FF_];
#pragma unroll
    for (int f = 0; f < FF_; ++f) {
        float a = b1[f];
#pragma unroll
        for (int j = 0; j < HID_; ++j)
            a = fmaf(W1[f * HID_ + j], hv[j], a);
        z[f] = fmaxf(a, 0.0f);
    }
#pragma unroll
    for (int cl = 0; cl < NCLS_; ++cl) {
        float a = b2[cl];
#pragma unroll
        for (int f = 0; f < FF_; ++f)
            a = fmaf(W2[cl * FF_ + f], z[f], a);
        out[(size_t)r * NCLS_ + cl] = a;
    }
}

// ---------------- K4: softmax over axis 0 (T), in place in d_out ------------
__global__ __launch_bounds__(224) void k_softmax(float* __restrict__ out)
{
    const int b    = blockIdx.x;
    const int cl   = threadIdx.x >> 5;     // 0..6
    const int lane = threadIdx.x & 31;

    float v[16];
#pragma unroll
    for (int j = 0; j < 16; ++j) {
        const int t = lane + j * 32;
        v[j] = out[((size_t)t * B_ + b) * NCLS_ + cl];
    }
    float m = v[0];
#pragma unroll
    for (int j = 1; j < 16; ++j) m = fmaxf(m, v[j]);
#pragma unroll
    for (int s = 16; s > 0; s >>= 1)
        m = fmaxf(m, __shfl_xor_sync(0xffffffff, m, s));

    float sum = 0.0f;
#pragma unroll
    for (int j = 0; j < 16; ++j) {
        v[j] = ex2f(1.4426950408889634f * (v[j] - m));
        sum += v[j];
    }
#pragma unroll
    for (int s = 16; s > 0; s >>= 1)
        sum += __shfl_xor_sync(0xffffffff, sum, s);

    const float r = 1.0f / sum;
#pragma unroll
    for (int j = 0; j < 16; ++j) {
        const int t = lane + j * 32;
        out[((size_t)t * B_ + b) * NCLS_ + cl] = v[j] * r;
    }
}

// ---------------- launch: bind by size + infer W-pair orientation -----------
// Unique sizes bind x, emb, W1, b1, W2, b2 regardless of listing order.
// {4096,4096} = {W_ih, W_hh}: if W1 (unique) appears BEFORE the pair, listing
// is name-sorted ("W1","W2","W_hh","W_ih") => W_hh first; otherwise (dict /
// signature / reverse-sorted) => W_ih first. Bias pair is sum-only.
extern "C" void kernel_launch(void* const* d_in, const int* in_sizes, int n_in,
                              void* d_out, int out_size)
{
    const int*   x    = nullptr;
    const float* emb  = nullptr;
    const float* Wp0  = nullptr;
    const float* Wp1  = nullptr;
    const float* b_ih = nullptr;
    const float* b_hh = nullptr;
    const float* W1   = nullptr;
    const float* b1   = nullptr;
    const float* W2   = nullptr;
    const float* b2   = nullptr;
    int idx_W1 = -1, idx_Wp0 = -1;

    for (int i = 0; i < n_in; ++i) {
        const int s = in_sizes[i];
        const void* p = d_in[i];
        switch (s) {
            case T_ * B_:
            case 2 * T_ * B_:
                if (!x) x = (const int*)p;
                break;
            case VOCAB_ * EMB_:
                emb = (const float*)p; break;
            case G4_ * EMB_:
                if (!Wp0) { Wp0 = (const float*)p; idx_Wp0 = i; }
                else      { Wp1 = (const float*)p; }
                break;
            case G4_:
                if (!b_ih) b_ih = (const float*)p; else b_hh = (const float*)p;
                break;
            case FF_ * HID_:
                W1 = (const float*)p; idx_W1 = i; break;
            case FF_:
                b1 = (const float*)p; break;
            case NCLS_ * FF_:
                W2 = (const float*)p; break;
            case NCLS_:
                b2 = (const float*)p; break;
            default: break;
        }
    }

    const bool sorted_order = (idx_W1 >= 0 && idx_Wp0 >= 0 && idx_W1 < idx_Wp0);
    const float* W_ih = sorted_order ? Wp1 : Wp0;
    const float* W_hh = sorted_order ? Wp0 : Wp1;

    float* out = (float*)d_out;

    k_lstm2   <<<B_ / 4, 128>>>(x, emb, W_ih, W_hh, b_ih, b_hh);
    k_ff2     <<<(T_ * B_) / 256, 256>>>(W1, b1, W2, b2, out);
    k_softmax <<<B_, 224>>>(out);
}

// round 6
// speedup vs baseline: 7.2968x; 7.2968x over previous
#include <cuda_runtime.h>
#include <cuda_bf16.h>

#define T_      512
#define B_      512
#define EMB_    32
#define HID_    32
#define G4_     128   // 4*HID
#define FF_     16
#define NCLS_   7
#define VOCAB_  1000

// ---------------- scratch (static device memory) ----------------------------
__device__ float g_tab[VOCAB_ * G4_];          // 512 KB: xg per vocab entry
__device__ float g_hs[(size_t)T_ * B_ * HID_]; // 32 MB hidden states

// ---------------- fast math --------------------------------------------------
__device__ __forceinline__ float ex2f(float x) {
    float r; asm("ex2.approx.f32 %0, %1;" : "=f"(r) : "f"(x)); return r;
}
__device__ __forceinline__ float rcpf(float x) {
    float r; asm("rcp.approx.f32 %0, %1;" : "=f"(r) : "f"(x)); return r;
}
// sigmoid(x) = 1/(1+2^(-x*log2e));  tanh(x) = 2/(1+2^(-2x*log2e)) - 1
__device__ __forceinline__ float sigm_f(float x) {
    return rcpf(1.0f + ex2f(-1.4426950408889634f * x));
}
__device__ __forceinline__ float tanh_f(float x) {
    return fmaf(2.0f, rcpf(1.0f + ex2f(-2.8853900817779268f * x)), -1.0f);
}

// ---- token dtype sniff: int64 tokens (<1000) have zero high words ----------
__device__ __forceinline__ bool x_is_i64(const int* __restrict__ x32) {
    return (x32[1] | x32[3] | x32[5] | x32[7] | x32[9]) == 0;
}
__device__ __forceinline__ int get_tok(const int* __restrict__ x32,
                                       bool i64, int idx) {
    return x32[i64 ? (idx << 1) : idx];
}

// ---------------- K1: gate table, trivial row-major layout ------------------
// g_tab[v][row] = W_ih[row,:] . emb[v,:] + b_ih[row] + b_hh[row],  row=0..127
__global__ __launch_bounds__(128) void k_table(
    const float* __restrict__ emb, const float* __restrict__ W_ih,
    const float* __restrict__ b_ih, const float* __restrict__ b_hh)
{
    __shared__ float e_sh[EMB_];
    const int v = blockIdx.x;
    const int row = threadIdx.x;          // 0..127
    if (row < EMB_) e_sh[row] = emb[v * EMB_ + row];
    __syncthreads();
    float acc = b_ih[row] + b_hh[row];
#pragma unroll
    for (int e = 0; e < EMB_; ++e)
        acc = fmaf(W_ih[row * EMB_ + e], e_sh[e], acc);
    g_tab[v * G4_ + row] = acc;
}

// ---------------- K2: LSTM, warp-per-batch, shfl recurrence -----------------
__global__ __launch_bounds__(128) void k_lstm3(
    const int* __restrict__ x, const float* __restrict__ W_hh)
{
    __shared__ int tok_s[4][T_];          // 8 KB: this block's token columns

    const int tid  = threadIdx.x;
    const int wid  = tid >> 5;
    const int lane = tid & 31;
    const int b    = blockIdx.x * 4 + wid;
    const bool i64 = x_is_i64(x);

    // one-time token staging (latency amortized over 512 steps)
    for (int i = lane; i < T_; i += 32)
        tok_s[wid][i] = get_tok(x, i64, i * B_ + b);

    // recurrent weights in registers: rows lane, 32+lane, 64+lane, 96+lane
    float Wi[HID_], Wf[HID_], Wg[HID_], Wo[HID_];
#pragma unroll
    for (int j = 0; j < HID_; ++j) {
        Wi[j] = W_hh[(0 * HID_ + lane) * HID_ + j];
        Wf[j] = W_hh[(1 * HID_ + lane) * HID_ + j];
        Wg[j] = W_hh[(2 * HID_ + lane) * HID_ + j];
        Wo[j] = W_hh[(3 * HID_ + lane) * HID_ + j];
    }
    __syncwarp();

    float h = 0.0f, c = 0.0f;

    // prefetch xg for t=0
    int tk = tok_s[wid][0];
    float ai_n = g_tab[tk * G4_ + 0 * HID_ + lane];
    float af_n = g_tab[tk * G4_ + 1 * HID_ + lane];
    float ag_n = g_tab[tk * G4_ + 2 * HID_ + lane];
    float ao_n = g_tab[tk * G4_ + 3 * HID_ + lane];

    for (int t = 0; t < T_; ++t) {
        float ai = ai_n, af = af_n, ag = ag_n, ao = ao_n;

        // prefetch next step's xg (t+1 wraps to 0 at the end: harmless dup)
        tk = tok_s[wid][(t + 1) & (T_ - 1)];
        ai_n = g_tab[tk * G4_ + 0 * HID_ + lane];
        af_n = g_tab[tk * G4_ + 1 * HID_ + lane];
        ag_n = g_tab[tk * G4_ + 2 * HID_ + lane];
        ao_n = g_tab[tk * G4_ + 3 * HID_ + lane];

        // recurrence: += W_hh[row, j] * h_j  (h_j broadcast via shfl)
#pragma unroll
        for (int j = 0; j < HID_; ++j) {
            const float hj = __shfl_sync(0xffffffffu, h, j);
            ai = fmaf(Wi[j], hj, ai);
            af = fmaf(Wf[j], hj, af);
            ag = fmaf(Wg[j], hj, ag);
            ao = fmaf(Wo[j], hj, ao);
        }

        const float ig = sigm_f(ai);
        const float fg = sigm_f(af);
        const float gg = tanh_f(ag);
        const float og = sigm_f(ao);
        c = fmaf(fg, c, ig * gg);
        h = og * tanh_f(c);

        g_hs[((size_t)t * B_ + b) * HID_ + lane] = h;  // coalesced 128B/warp
    }
}

// ---------------- K3: FF + logits -------------------------------------------
__global__ __launch_bounds__(256) void k_ff2(
    const float* __restrict__ W1, const float* __restrict__ b1,
    const float* __restrict__ W2, const float* __restrict__ b2,
    float* __restrict__ out)
{
    const int r = blockIdx.x * 256 + threadIdx.x;      // flat row t*B+b
    float hv[HID_];
    const float4* hp = reinterpret_cast<const float4*>(&g_hs[(size_t)r * HID_]);
#pragma unroll
    for (int q = 0; q < HID_ / 4; ++q) {
        const float4 v = hp[q];
        hv[q * 4 + 0] = v.x; hv[q * 4 + 1] = v.y;
        hv[q * 4 + 2] = v.z; hv[q * 4 + 3] = v.w;
    }
    float z[FF_];
#pragma unroll
    for (int f = 0; f < FF_; ++f) {
        float a = b1[f];
#pragma unroll
        for (int j = 0; j < HID_; ++j)
            a = fmaf(W1[f * HID_ + j], hv[j], a);
        z[f] = fmaxf(a, 0.0f);
    }
#pragma unroll
    for (int cl = 0; cl < NCLS_; ++cl) {
        float a = b2[cl];
#pragma unroll
        for (int f = 0; f < FF_; ++f)
            a = fmaf(W2[cl * FF_ + f], z[f], a);
        out[(size_t)r * NCLS_ + cl] = a;
    }
}

// ---------------- K4: softmax over axis 0 (T), in place in d_out ------------
__global__ __launch_bounds__(224) void k_softmax(float* __restrict__ out)
{
    const int b    = blockIdx.x;
    const int cl   = threadIdx.x >> 5;     // 0..6
    const int lane = threadIdx.x & 31;

    float v[16];
#pragma unroll
    for (int j = 0; j < 16; ++j) {
        const int t = lane + j * 32;
        v[j] = out[((size_t)t * B_ + b) * NCLS_ + cl];
    }
    float m = v[0];
#pragma unroll
    for (int j = 1; j < 16; ++j) m = fmaxf(m, v[j]);
#pragma unroll
    for (int s = 16; s > 0; s >>= 1)
        m = fmaxf(m, __shfl_xor_sync(0xffffffff, m, s));

    float sum = 0.0f;
#pragma unroll
    for (int j = 0; j < 16; ++j) {
        v[j] = ex2f(1.4426950408889634f * (v[j] - m));
        sum += v[j];
    }
#pragma unroll
    for (int s = 16; s > 0; s >>= 1)
        sum += __shfl_xor_sync(0xffffffff, sum, s);

    const float r = 1.0f / sum;
#pragma unroll
    for (int j = 0; j < 16; ++j) {
        const int t = lane + j * 32;
        out[((size_t)t * B_ + b) * NCLS_ + cl] = v[j] * r;
    }
}

// ---------------- launch: bind by size + infer W-pair orientation -----------
// (identical to the R5 binding that passed)
extern "C" void kernel_launch(void* const* d_in, const int* in_sizes, int n_in,
                              void* d_out, int out_size)
{
    const int*   x    = nullptr;
    const float* emb  = nullptr;
    const float* Wp0  = nullptr;
    const float* Wp1  = nullptr;
    const float* b_ih = nullptr;
    const float* b_hh = nullptr;
    const float* W1   = nullptr;
    const float* b1   = nullptr;
    const float* W2   = nullptr;
    const float* b2   = nullptr;
    int idx_W1 = -1, idx_Wp0 = -1;

    for (int i = 0; i < n_in; ++i) {
        const int s = in_sizes[i];
        const void* p = d_in[i];
        switch (s) {
            case T_ * B_:
            case 2 * T_ * B_:
                if (!x) x = (const int*)p;
                break;
            case VOCAB_ * EMB_:
                emb = (const float*)p; break;
            case G4_ * EMB_:
                if (!Wp0) { Wp0 = (const float*)p; idx_Wp0 = i; }
                else      { Wp1 = (const float*)p; }
                break;
            case G4_:
                if (!b_ih) b_ih = (const float*)p; else b_hh = (const float*)p;
                break;
            case FF_ * HID_:
                W1 = (const float*)p; idx_W1 = i; break;
            case FF_:
                b1 = (const float*)p; break;
            case NCLS_ * FF_:
                W2 = (const float*)p; break;
            case NCLS_:
                b2 = (const float*)p; break;
            default: break;
        }
    }

    const bool sorted_order = (idx_W1 >= 0 && idx_Wp0 >= 0 && idx_W1 < idx_Wp0);
    const float* W_ih = sorted_order ? Wp1 : Wp0;
    const float* W_hh = sorted_order ? Wp0 : Wp1;

    float* out = (float*)d_out;

    k_table   <<<VOCAB_, 128>>>(emb, W_ih, b_ih, b_hh);
    k_lstm3   <<<B_ / 4, 128>>>(x, W_hh);
    k_ff2     <<<(T_ * B_) / 256, 256>>>(W1, b1, W2, b2, out);
    k_softmax <<<B_, 224>>>(out);
}